// round 8
// baseline (speedup 1.0000x reference)
#include <cuda_runtime.h>
#include <math.h>

static constexpr int BB = 8;
static constexpr int CC = 96;
static constexpr int C2 = 192;
static constexpr int C4 = 384;
static constexpr int NN = 3136;   // 56*56
static constexpr int KK = 9;
static constexpr float EPS_ = 1e-5f;

// ---------------- scratch (no allocations allowed) ----------------
__device__ float g_act[BB * CC * NN];
__device__ float g_t1 [BB * CC * NN];
__device__ float g_xf [BB * CC * NN];
__device__ float g_xn [BB * CC * NN];
__device__ float g_sq [BB * NN];
__device__ int   g_idx[BB * NN * KK];
__device__ float g_big[BB * C4 * NN];   // ffn hidden; also 2C y2 + 2C t3 for grapher

// ---------------- packed f32x2 helpers (FFMA2 via PTX) ----------------
typedef unsigned long long ull;
__device__ __forceinline__ ull pack2(float lo, float hi) {
    ull r;
    asm("mov.b64 %0, {%1, %2};" : "=l"(r) : "f"(lo), "f"(hi));
    return r;
}
__device__ __forceinline__ void ffma2(ull& d, ull a, ull b) {
    asm("fma.rn.f32x2 %0, %1, %2, %3;" : "=l"(d) : "l"(a), "l"(b), "l"(d));
}
__device__ __forceinline__ float2 unpack2(ull v) {
    float2 f;
    asm("mov.b64 {%0, %1}, %2;" : "=f"(f.x), "=f"(f.y) : "l"(v));
    return f;
}

// ---------------- 1x1 conv == batched GEMM: out[b,o,n] = sum_c W[o,c] X[b,c,n] + bias[o]
// 128 threads, 64x64 tile, thread = 4 o-rows x 8 n-cols (4 f32x2 pairs)
__global__ __launch_bounds__(128) void gemm_bias_kernel(
    const float* __restrict__ X, const float* __restrict__ W,
    const float* __restrict__ bias, float* __restrict__ out,
    int Cout, int Cin)
{
    int b  = blockIdx.z;
    int n0 = blockIdx.x * 64;
    int o0 = blockIdx.y * 64;
    int tid = threadIdx.x;
    int ty4 = (tid >> 3) * 4;   // 0..60 step 4
    int tx4 = (tid & 7) * 4;    // 0..28 step 4
    __shared__ float Ws[32][64];   // [k][o]
    __shared__ float Xs[32][64];   // [k][n]
    ull acc[4][4];
    #pragma unroll
    for (int i = 0; i < 4; i++)
        #pragma unroll
        for (int j = 0; j < 4; j++) acc[i][j] = 0ull;
    const float* Xb = X + (size_t)b * Cin * NN;

    for (int kt = 0; kt < Cin; kt += 32) {
        for (int t = tid; t < 512; t += 128) {
            int o = t & 63, kq = t >> 6;
            float4 w = make_float4(0.f, 0.f, 0.f, 0.f);
            if (o0 + o < Cout)
                w = *(const float4*)&W[(size_t)(o0 + o) * Cin + kt + kq * 4];
            Ws[kq * 4 + 0][o] = w.x;
            Ws[kq * 4 + 1][o] = w.y;
            Ws[kq * 4 + 2][o] = w.z;
            Ws[kq * 4 + 3][o] = w.w;
        }
        for (int t = tid; t < 512; t += 128) {
            int k = t >> 4, nq = t & 15;
            *(float4*)&Xs[k][nq * 4] =
                *(const float4*)&Xb[(size_t)(kt + k) * NN + n0 + nq * 4];
        }
        __syncthreads();
        #pragma unroll 8
        for (int k = 0; k < 32; k++) {
            float4 a = *(const float4*)&Ws[k][ty4];           // quarter-warp broadcast
            ulonglong2 bl = *(const ulonglong2*)&Xs[k][tx4];  // free f32x2 pairs
            ulonglong2 br = *(const ulonglong2*)&Xs[k][32 + tx4];
            ull bp[4] = {bl.x, bl.y, br.x, br.y};
            ull ap[4] = {pack2(a.x, a.x), pack2(a.y, a.y),
                         pack2(a.z, a.z), pack2(a.w, a.w)};
            #pragma unroll
            for (int i = 0; i < 4; i++)
                #pragma unroll
                for (int j = 0; j < 4; j++)
                    ffma2(acc[i][j], ap[i], bp[j]);
        }
        __syncthreads();
    }
    #pragma unroll
    for (int i = 0; i < 4; i++) {
        int o = o0 + ty4 + i;
        if (o < Cout) {
            float bvv = bias[o];
            float* op = out + ((size_t)b * Cout + o) * NN + n0;
            float2 p0 = unpack2(acc[i][0]), p1 = unpack2(acc[i][1]);
            float2 p2 = unpack2(acc[i][2]), p3 = unpack2(acc[i][3]);
            *(float4*)&op[tx4] =
                make_float4(p0.x + bvv, p0.y + bvv, p1.x + bvv, p1.y + bvv);
            *(float4*)&op[32 + tx4] =
                make_float4(p2.x + bvv, p2.y + bvv, p3.x + bvv, p3.y + bvv);
        }
    }
}

// ---------------- instance norm per (b,c) row over N; optional act + residual
// act: 0 none, 1 exact gelu, 2 relu   (NN % 4 == 0; all buffers 16B-aligned)
__global__ __launch_bounds__(256) void inorm_kernel(
    const float* __restrict__ in, float* __restrict__ out,
    const float* __restrict__ res, int act)
{
    int row = blockIdx.x;
    const float* p = in + (size_t)row * NN;
    int tid = threadIdx.x;
    float s = 0.f, s2 = 0.f;
    for (int i = tid * 4; i < NN; i += 1024) {
        float4 v = *(const float4*)&p[i];
        s  += v.x + v.y + v.z + v.w;
        s2 += v.x * v.x + v.y * v.y + v.z * v.z + v.w * v.w;
    }
    __shared__ float r0s[256], r1s[256];
    r0s[tid] = s; r1s[tid] = s2;
    __syncthreads();
    for (int st = 128; st > 0; st >>= 1) {
        if (tid < st) { r0s[tid] += r0s[tid + st]; r1s[tid] += r1s[tid + st]; }
        __syncthreads();
    }
    __shared__ float msh, rsh;
    if (tid == 0) {
        float mean = r0s[0] * (1.f / NN);
        float var  = r1s[0] * (1.f / NN) - mean * mean;
        msh = mean; rsh = rsqrtf(var + EPS_);
    }
    __syncthreads();
    float mean = msh, rstd = rsh;
    const float* rq = res ? res + (size_t)row * NN : nullptr;
    float* op = out + (size_t)row * NN;
    for (int i = tid * 4; i < NN; i += 1024) {
        float4 v = *(const float4*)&p[i];
        float vv[4] = {v.x, v.y, v.z, v.w};
        #pragma unroll
        for (int q = 0; q < 4; q++) {
            float u = (vv[q] - mean) * rstd;
            if (act == 1) u = 0.5f * u * (1.f + erff(u * 0.70710678118654752f));
            else if (act == 2) u = fmaxf(u, 0.f);
            vv[q] = u;
        }
        if (rq) {
            float4 r = *(const float4*)&rq[i];
            vv[0] += r.x; vv[1] += r.y; vv[2] += r.z; vv[3] += r.w;
        }
        *(float4*)&op[i] = make_float4(vv[0], vv[1], vv[2], vv[3]);
    }
}

// ---------------- l2 normalize over channel dim per (b,n); also emit sq = ||xn||^2
__global__ __launch_bounds__(256) void l2norm_kernel(
    const float* __restrict__ xf, float* __restrict__ xn, float* __restrict__ sq)
{
    int t = blockIdx.x * 256 + threadIdx.x;
    if (t >= BB * NN) return;
    int b = t / NN, n = t - b * NN;
    const float* p = xf + (size_t)b * CC * NN + n;
    float s = 0.f;
    #pragma unroll 16
    for (int c = 0; c < CC; c++) { float v = p[(size_t)c * NN]; s += v * v; }
    float inv = 1.f / fmaxf(sqrtf(s), 1e-12f);
    float* q = xn + (size_t)b * CC * NN + n;
    #pragma unroll 16
    for (int c = 0; c < CC; c++) q[(size_t)c * NN] = p[(size_t)c * NN] * inv;
    sq[t] = s * inv * inv;
}

// ---------------- fused pairwise distance + top-9 smallest
// 256 threads, 64 n-rows per block, m-tiles of 64
// thread = 2 n-rows x 8 m-cols; a = LDS.64 (8-lane broadcast),
// b = 2x LDS.128 as f32x2 pairs; FFMA2 mainloop.
// __launch_bounds__(256,3): 3 blocks/SM -> all 392 blocks in one wave.
__device__ __forceinline__ void tk_insert(float v, int m, float* tv, int* ti,
                                          float& wv, int& wi)
{
    if (v < wv) {
        tv[wi] = v; ti[wi] = m;
        wv = tv[0]; wi = 0;
        #pragma unroll
        for (int k = 1; k < KK; k++) if (tv[k] > wv) { wv = tv[k]; wi = k; }
    }
}

__global__ __launch_bounds__(256, 3) void dist_topk_kernel(
    const float* __restrict__ xn, const float* __restrict__ sq,
    const float* __restrict__ rp, int* __restrict__ oidx)
{
    int b = blockIdx.y;
    int n0 = blockIdx.x * 64;
    int tid = threadIdx.x;
    int mr  = tid >> 3;        // 0..31
    int mc4 = (tid & 7) * 4;   // 0..28
    int r0 = mr * 2, r1 = r0 + 1;

    __shared__ float Xn_s[CC * 64];   // 24 KB, [c][64 n-rows]
    __shared__ float sh2[CC * 64];    // 24 KB, [c][64 m]; reused for merge

    const float* xb = xn + (size_t)b * CC * NN;
    for (int t = tid; t < CC * 16; t += 256) {
        int c = t >> 4, q = (t & 15) * 4;
        *(float4*)&Xn_s[c * 64 + q] = *(const float4*)&xb[(size_t)c * NN + n0 + q];
    }
    __syncthreads();

    float2 sqn2 = *(const float2*)&sq[b * NN + n0 + r0];
    float sqn0 = sqn2.x, sqn1 = sqn2.y;

    float tv0[KK], tv1[KK]; int ti0[KK], ti1[KK];
    #pragma unroll
    for (int k = 0; k < KK; k++) { tv0[k] = 1e30f; tv1[k] = 1e30f; ti0[k] = 0; ti1[k] = 0; }
    float wv0 = 1e30f, wv1 = 1e30f; int wi0 = 0, wi1 = 0;

    for (int m0 = 0; m0 < NN; m0 += 64) {
        __syncthreads();
        for (int t = tid; t < CC * 16; t += 256) {
            int c = t >> 4, q = (t & 15) * 4;
            *(float4*)&sh2[c * 64 + q] = *(const float4*)&xb[(size_t)c * NN + m0 + q];
        }
        __syncthreads();
        ull acc[2][4];
        #pragma unroll
        for (int i = 0; i < 2; i++)
            #pragma unroll
            for (int j = 0; j < 4; j++) acc[i][j] = 0ull;
        #pragma unroll 8
        for (int c = 0; c < CC; c++) {
            float2 a = *(const float2*)&Xn_s[c * 64 + r0];              // broadcast
            ulonglong2 blp = *(const ulonglong2*)&sh2[c * 64 + mc4];    // free pairs
            ulonglong2 brp = *(const ulonglong2*)&sh2[c * 64 + 32 + mc4];
            ull bp[4] = {blp.x, blp.y, brp.x, brp.y};
            ull a0 = pack2(a.x, a.x), a1 = pack2(a.y, a.y);
            #pragma unroll
            for (int j = 0; j < 4; j++) {
                ffma2(acc[0][j], a0, bp[j]);
                ffma2(acc[1][j], a1, bp[j]);
            }
        }
        // epilogue: dist + topk insert (all 16B-aligned vector loads)
        const float* sqm = sq + b * NN + m0;
        float4 sqL = *(const float4*)&sqm[mc4];
        float4 sqR = *(const float4*)&sqm[32 + mc4];
        float sv[8] = {sqL.x, sqL.y, sqL.z, sqL.w, sqR.x, sqR.y, sqR.z, sqR.w};
        const float* rpr0 = rp + (size_t)(n0 + r0) * NN + m0;
        const float* rpr1 = rp + (size_t)(n0 + r1) * NN + m0;
        float4 rp0L = *(const float4*)&rpr0[mc4];
        float4 rp0R = *(const float4*)&rpr0[32 + mc4];
        float4 rp1L = *(const float4*)&rpr1[mc4];
        float4 rp1R = *(const float4*)&rpr1[32 + mc4];
        float r0v[8] = {rp0L.x, rp0L.y, rp0L.z, rp0L.w, rp0R.x, rp0R.y, rp0R.z, rp0R.w};
        float r1v[8] = {rp1L.x, rp1L.y, rp1L.z, rp1L.w, rp1R.x, rp1R.y, rp1R.z, rp1R.w};
        float2 d00 = unpack2(acc[0][0]), d01 = unpack2(acc[0][1]);
        float2 d02 = unpack2(acc[0][2]), d03 = unpack2(acc[0][3]);
        float2 d10 = unpack2(acc[1][0]), d11 = unpack2(acc[1][1]);
        float2 d12 = unpack2(acc[1][2]), d13 = unpack2(acc[1][3]);
        float dot0[8] = {d00.x, d00.y, d01.x, d01.y, d02.x, d02.y, d03.x, d03.y};
        float dot1[8] = {d10.x, d10.y, d11.x, d11.y, d12.x, d12.y, d13.x, d13.y};
        #pragma unroll
        for (int j = 0; j < 8; j++) {
            int m = m0 + (j < 4 ? mc4 + j : 32 + mc4 + (j - 4));
            float dd0 = fmaf(-2.f, dot0[j], sqn0 + sv[j] + r0v[j]);
            float dd1 = fmaf(-2.f, dot1[j], sqn1 + sv[j] + r1v[j]);
            tk_insert(dd0, m, tv0, ti0, wv0, wi0);
            tk_insert(dd1, m, tv1, ti1, wv1, wi1);
        }
    }

    // ---------- merge: two passes of 32 rows using sh2 ----------
    __syncthreads();
    float* cv = sh2;                          // [32][8][9] values
    int*   ci = (int*)(sh2 + 32 * 8 * KK);    // [32][8][9] indices
    int mc = tid & 7;
    #pragma unroll 1
    for (int pass = 0; pass < 2; pass++) {
        if ((mr >> 4) == pass) {
            int lr = r0 - pass * 32;          // 0..30 step 2
            #pragma unroll
            for (int k = 0; k < KK; k++) {
                cv[((lr + 0) * 8 + mc) * KK + k] = tv0[k];
                ci[((lr + 0) * 8 + mc) * KK + k] = ti0[k];
                cv[((lr + 1) * 8 + mc) * KK + k] = tv1[k];
                ci[((lr + 1) * 8 + mc) * KK + k] = ti1[k];
            }
        }
        __syncthreads();
        if (tid < 32) {
            float* rv = cv + tid * 8 * KK;
            int*   ri = ci + tid * 8 * KK;
            int* op = oidx + ((size_t)b * NN + n0 + pass * 32 + tid) * KK;
            for (int k = 0; k < KK; k++) {
                float best = 2e30f; int bi = 0, bt = 0;
                for (int t = 0; t < 8 * KK; t++) {
                    float v = rv[t];
                    if (v < best) { best = v; bi = ri[t]; bt = t; }
                }
                rv[bt] = 3e30f;   // consume
                op[k] = bi;
            }
        }
        __syncthreads();
    }
}

// ---------------- gather neighbors, max(x_j - x_i), write channel-interleaved (B,2C,N)
__global__ __launch_bounds__(256) void aggregate_kernel(
    const float* __restrict__ xf, const int* __restrict__ idx, float* __restrict__ y)
{
    int bc = blockIdx.x;            // b*CC + c
    __shared__ float row[NN];
    const float* p = xf + (size_t)bc * NN;
    for (int i = threadIdx.x; i < NN; i += 256) row[i] = p[i];
    __syncthreads();
    int b = bc / CC, c = bc - b * CC;
    const int* ip = idx + (size_t)b * NN * KK;
    float* y0 = y + ((size_t)b * C2 + 2 * c) * NN;
    float* y1 = y0 + NN;
    for (int n = threadIdx.x; n < NN; n += 256) {
        float xi = row[n];
        float mx = -3e38f;
        #pragma unroll
        for (int k = 0; k < KK; k++) {
            int j = ip[n * KK + k];
            mx = fmaxf(mx, row[j] - xi);
        }
        y0[n] = xi;
        y1[n] = mx;
    }
}

// ---------------- host orchestration ----------------
static void run_conv(const float* X, const float* W, const float* bias,
                     float* out, int Cout, int Cin)
{
    dim3 g(NN / 64, (Cout + 63) / 64, BB);
    gemm_bias_kernel<<<g, 128>>>(X, W, bias, out, Cout, Cin);
}
static void run_inorm(const float* in, float* out, const float* res, int Crows, int act)
{
    inorm_kernel<<<BB * Crows, 256>>>(in, out, res, act);
}

extern "C" void kernel_launch(void* const* d_in, const int* in_sizes, int n_in,
                              void* d_out, int out_size)
{
    (void)in_sizes; (void)n_in; (void)out_size;
    const float* x  = (const float*)d_in[0];
    const float* rp = (const float*)d_in[1];
    const float* P[20];
    for (int i = 0; i < 20; i++) P[i] = (const float*)d_in[2 + i];

    float *act, *t1, *xf, *xnp, *sqp, *big; int* idxp;
    cudaGetSymbolAddress((void**)&act,  g_act);
    cudaGetSymbolAddress((void**)&t1,   g_t1);
    cudaGetSymbolAddress((void**)&xf,   g_xf);
    cudaGetSymbolAddress((void**)&xnp,  g_xn);
    cudaGetSymbolAddress((void**)&sqp,  g_sq);
    cudaGetSymbolAddress((void**)&idxp, g_idx);
    cudaGetSymbolAddress((void**)&big,  g_big);
    float* y2 = big;                          // (B,2C,N)
    float* t3 = big + (size_t)BB * C2 * NN;   // (B,2C,N)
    float* out = (float*)d_out;

    auto grapher = [&](const float* inx,
                       const float* w1, const float* b1,
                       const float* mw, const float* mb,
                       const float* w2, const float* b2, float* outp) {
        run_conv(inx, w1, b1, t1, CC, CC);
        run_inorm(t1, xf, nullptr, CC, 0);                          // xf
        l2norm_kernel<<<(BB * NN + 255) / 256, 256>>>(xf, xnp, sqp);
        dim3 dg(NN / 64, BB);
        dist_topk_kernel<<<dg, 256>>>(xnp, sqp, rp, idxp);
        aggregate_kernel<<<BB * CC, 256>>>(xf, idxp, y2);           // (B,2C,N)
        run_conv(y2, mw, mb, t3, C2, C2);
        run_inorm(t3, t3, nullptr, C2, 1);                          // gelu, in-place
        run_conv(t3, w2, b2, t1, CC, C2);
        run_inorm(t1, outp, inx, CC, 0);                            // + shortcut
    };
    auto ffn = [&](float* a, const float* w1, const float* b1,
                   const float* w2, const float* b2) {
        run_conv(a, w1, b1, big, C4, CC);
        run_inorm(big, big, nullptr, C4, 1);                        // gelu, in-place
        run_conv(big, w2, b2, t1, CC, C4);
        run_inorm(t1, a, a, CC, 0);                                 // + shortcut
    };

    grapher(x, P[0], P[1], P[2], P[3], P[4], P[5], act);
    ffn(act, P[12], P[13], P[14], P[15]);
    run_inorm(act, act, nullptr, CC, 2);                            // relu(inorm)
    grapher(act, P[6], P[7], P[8], P[9], P[10], P[11], act);
    ffn(act, P[16], P[17], P[18], P[19]);
    run_inorm(act, out, x, CC, 0);                                  // x + inorm(y)
}

// round 9
// speedup vs baseline: 1.0369x; 1.0369x over previous
#include <cuda_runtime.h>
#include <math.h>

static constexpr int BB = 8;
static constexpr int CC = 96;
static constexpr int C2 = 192;
static constexpr int C4 = 384;
static constexpr int NN = 3136;   // 56*56
static constexpr int KK = 9;
static constexpr float EPS_ = 1e-5f;
static constexpr int MSPLIT0 = 1600;   // half 0: [0,1600), half 1: [1600,3136)

// ---------------- scratch (no allocations allowed) ----------------
__device__ float g_act[BB * CC * NN];
__device__ float g_t1 [BB * CC * NN];
__device__ float g_xf [BB * CC * NN];
__device__ float g_xn [BB * CC * NN];
__device__ float g_sq [BB * NN];
__device__ int   g_idx[BB * NN * KK];
__device__ float g_pv [BB * NN * 2 * KK];   // partial top-9 values
__device__ int   g_pi [BB * NN * 2 * KK];   // partial top-9 indices
__device__ float g_big[BB * C4 * NN];   // ffn hidden; also 2C y2 + 2C t3 for grapher

// ---------------- packed f32x2 helpers (FFMA2 via PTX) ----------------
typedef unsigned long long ull;
__device__ __forceinline__ ull pack2(float lo, float hi) {
    ull r;
    asm("mov.b64 %0, {%1, %2};" : "=l"(r) : "f"(lo), "f"(hi));
    return r;
}
__device__ __forceinline__ void ffma2(ull& d, ull a, ull b) {
    asm("fma.rn.f32x2 %0, %1, %2, %3;" : "=l"(d) : "l"(a), "l"(b), "l"(d));
}
__device__ __forceinline__ float2 unpack2(ull v) {
    float2 f;
    asm("mov.b64 {%0, %1}, %2;" : "=f"(f.x), "=f"(f.y) : "l"(v));
    return f;
}

// ---------------- 1x1 conv == batched GEMM: out[b,o,n] = sum_c W[o,c] X[b,c,n] + bias[o]
// 128 threads, 64x64 tile, thread = 4 o-rows x 8 n-cols (4 f32x2 pairs)
__global__ __launch_bounds__(128) void gemm_bias_kernel(
    const float* __restrict__ X, const float* __restrict__ W,
    const float* __restrict__ bias, float* __restrict__ out,
    int Cout, int Cin)
{
    int b  = blockIdx.z;
    int n0 = blockIdx.x * 64;
    int o0 = blockIdx.y * 64;
    int tid = threadIdx.x;
    int ty4 = (tid >> 3) * 4;   // 0..60 step 4
    int tx4 = (tid & 7) * 4;    // 0..28 step 4
    __shared__ float Ws[32][64];   // [k][o]
    __shared__ float Xs[32][64];   // [k][n]
    ull acc[4][4];
    #pragma unroll
    for (int i = 0; i < 4; i++)
        #pragma unroll
        for (int j = 0; j < 4; j++) acc[i][j] = 0ull;
    const float* Xb = X + (size_t)b * Cin * NN;

    for (int kt = 0; kt < Cin; kt += 32) {
        for (int t = tid; t < 512; t += 128) {
            int o = t & 63, kq = t >> 6;
            float4 w = make_float4(0.f, 0.f, 0.f, 0.f);
            if (o0 + o < Cout)
                w = *(const float4*)&W[(size_t)(o0 + o) * Cin + kt + kq * 4];
            Ws[kq * 4 + 0][o] = w.x;
            Ws[kq * 4 + 1][o] = w.y;
            Ws[kq * 4 + 2][o] = w.z;
            Ws[kq * 4 + 3][o] = w.w;
        }
        for (int t = tid; t < 512; t += 128) {
            int k = t >> 4, nq = t & 15;
            *(float4*)&Xs[k][nq * 4] =
                *(const float4*)&Xb[(size_t)(kt + k) * NN + n0 + nq * 4];
        }
        __syncthreads();
        #pragma unroll 8
        for (int k = 0; k < 32; k++) {
            float4 a = *(const float4*)&Ws[k][ty4];           // quarter-warp broadcast
            ulonglong2 bl = *(const ulonglong2*)&Xs[k][tx4];  // free f32x2 pairs
            ulonglong2 br = *(const ulonglong2*)&Xs[k][32 + tx4];
            ull bp[4] = {bl.x, bl.y, br.x, br.y};
            ull ap[4] = {pack2(a.x, a.x), pack2(a.y, a.y),
                         pack2(a.z, a.z), pack2(a.w, a.w)};
            #pragma unroll
            for (int i = 0; i < 4; i++)
                #pragma unroll
                for (int j = 0; j < 4; j++)
                    ffma2(acc[i][j], ap[i], bp[j]);
        }
        __syncthreads();
    }
    #pragma unroll
    for (int i = 0; i < 4; i++) {
        int o = o0 + ty4 + i;
        if (o < Cout) {
            float bvv = bias[o];
            float* op = out + ((size_t)b * Cout + o) * NN + n0;
            float2 p0 = unpack2(acc[i][0]), p1 = unpack2(acc[i][1]);
            float2 p2 = unpack2(acc[i][2]), p3 = unpack2(acc[i][3]);
            *(float4*)&op[tx4] =
                make_float4(p0.x + bvv, p0.y + bvv, p1.x + bvv, p1.y + bvv);
            *(float4*)&op[32 + tx4] =
                make_float4(p2.x + bvv, p2.y + bvv, p3.x + bvv, p3.y + bvv);
        }
    }
}

// ---------------- instance norm per (b,c) row over N; optional act + residual
// act: 0 none, 1 exact gelu, 2 relu   (NN % 4 == 0; all buffers 16B-aligned)
__global__ __launch_bounds__(256) void inorm_kernel(
    const float* __restrict__ in, float* __restrict__ out,
    const float* __restrict__ res, int act)
{
    int row = blockIdx.x;
    const float* p = in + (size_t)row * NN;
    int tid = threadIdx.x;
    float s = 0.f, s2 = 0.f;
    for (int i = tid * 4; i < NN; i += 1024) {
        float4 v = *(const float4*)&p[i];
        s  += v.x + v.y + v.z + v.w;
        s2 += v.x * v.x + v.y * v.y + v.z * v.z + v.w * v.w;
    }
    __shared__ float r0s[256], r1s[256];
    r0s[tid] = s; r1s[tid] = s2;
    __syncthreads();
    for (int st = 128; st > 0; st >>= 1) {
        if (tid < st) { r0s[tid] += r0s[tid + st]; r1s[tid] += r1s[tid + st]; }
        __syncthreads();
    }
    __shared__ float msh, rsh;
    if (tid == 0) {
        float mean = r0s[0] * (1.f / NN);
        float var  = r1s[0] * (1.f / NN) - mean * mean;
        msh = mean; rsh = rsqrtf(var + EPS_);
    }
    __syncthreads();
    float mean = msh, rstd = rsh;
    const float* rq = res ? res + (size_t)row * NN : nullptr;
    float* op = out + (size_t)row * NN;
    for (int i = tid * 4; i < NN; i += 1024) {
        float4 v = *(const float4*)&p[i];
        float vv[4] = {v.x, v.y, v.z, v.w};
        #pragma unroll
        for (int q = 0; q < 4; q++) {
            float u = (vv[q] - mean) * rstd;
            if (act == 1) u = 0.5f * u * (1.f + erff(u * 0.70710678118654752f));
            else if (act == 2) u = fmaxf(u, 0.f);
            vv[q] = u;
        }
        if (rq) {
            float4 r = *(const float4*)&rq[i];
            vv[0] += r.x; vv[1] += r.y; vv[2] += r.z; vv[3] += r.w;
        }
        *(float4*)&op[i] = make_float4(vv[0], vv[1], vv[2], vv[3]);
    }
}

// ---------------- l2 normalize over channel dim per (b,n); also emit sq = ||xn||^2
__global__ __launch_bounds__(256) void l2norm_kernel(
    const float* __restrict__ xf, float* __restrict__ xn, float* __restrict__ sq)
{
    int t = blockIdx.x * 256 + threadIdx.x;
    if (t >= BB * NN) return;
    int b = t / NN, n = t - b * NN;
    const float* p = xf + (size_t)b * CC * NN + n;
    float s = 0.f;
    #pragma unroll 16
    for (int c = 0; c < CC; c++) { float v = p[(size_t)c * NN]; s += v * v; }
    float inv = 1.f / fmaxf(sqrtf(s), 1e-12f);
    float* q = xn + (size_t)b * CC * NN + n;
    #pragma unroll 16
    for (int c = 0; c < CC; c++) q[(size_t)c * NN] = p[(size_t)c * NN] * inv;
    sq[t] = s * inv * inv;
}

// ---------------- fused pairwise distance + partial top-9 (m-split halves)
// R6 config: 128 threads, 64 n-rows, thread = 4 n-rows x 8 m-cols, FFMA2 mainloop.
// grid = (NN/64, 2 halves, BB); each block scans its m-half, writes top-9 (v,i).
__device__ __forceinline__ void tk_insert(float v, int m, float* tv, int* ti,
                                          float& wv, int& wi)
{
    if (v < wv) {
        tv[wi] = v; ti[wi] = m;
        wv = tv[0]; wi = 0;
        #pragma unroll
        for (int k = 1; k < KK; k++) if (tv[k] > wv) { wv = tv[k]; wi = k; }
    }
}

__global__ __launch_bounds__(128) void dist_topk_kernel(
    const float* __restrict__ xn, const float* __restrict__ sq,
    const float* __restrict__ rp, float* __restrict__ pv, int* __restrict__ pi)
{
    int b = blockIdx.z;
    int half = blockIdx.y;
    int n0 = blockIdx.x * 64;
    int mstart = half ? MSPLIT0 : 0;
    int mend   = half ? NN : MSPLIT0;
    int tid = threadIdx.x;
    int mr  = tid >> 3;        // 0..15
    int mc4 = (tid & 7) * 4;   // 0..28
    int rbase = mr * 4;        // rows rbase..rbase+3 (0..63)

    __shared__ float Xn_s[CC * 64];   // 24 KB, [c][64 n-rows]
    __shared__ float sh2[CC * 64];    // 24 KB, [c][64 m]; reused for merge

    const float* xb = xn + (size_t)b * CC * NN;
    for (int t = tid; t < CC * 16; t += 128) {
        int c = t >> 4, q = (t & 15) * 4;
        *(float4*)&Xn_s[c * 64 + q] = *(const float4*)&xb[(size_t)c * NN + n0 + q];
    }
    __syncthreads();

    float4 sqn4 = *(const float4*)&sq[b * NN + n0 + rbase];
    float sqn[4] = {sqn4.x, sqn4.y, sqn4.z, sqn4.w};

    float tv[4][KK]; int ti[4][KK];
    float wv[4]; int wi[4];
    #pragma unroll
    for (int i = 0; i < 4; i++) {
        #pragma unroll
        for (int k = 0; k < KK; k++) { tv[i][k] = 1e30f; ti[i][k] = 0; }
        wv[i] = 1e30f; wi[i] = 0;
    }

    for (int m0 = mstart; m0 < mend; m0 += 64) {
        __syncthreads();
        for (int t = tid; t < CC * 16; t += 128) {
            int c = t >> 4, q = (t & 15) * 4;
            *(float4*)&sh2[c * 64 + q] = *(const float4*)&xb[(size_t)c * NN + m0 + q];
        }
        __syncthreads();
        ull acc[4][4];
        #pragma unroll
        for (int i = 0; i < 4; i++)
            #pragma unroll
            for (int j = 0; j < 4; j++) acc[i][j] = 0ull;
        #pragma unroll 4
        for (int c = 0; c < CC; c++) {
            float4 a = *(const float4*)&Xn_s[c * 64 + rbase];           // broadcast
            ulonglong2 blp = *(const ulonglong2*)&sh2[c * 64 + mc4];    // free pairs
            ulonglong2 brp = *(const ulonglong2*)&sh2[c * 64 + 32 + mc4];
            ull bp[4] = {blp.x, blp.y, brp.x, brp.y};
            ull ap[4] = {pack2(a.x, a.x), pack2(a.y, a.y),
                         pack2(a.z, a.z), pack2(a.w, a.w)};
            #pragma unroll
            for (int i = 0; i < 4; i++)
                #pragma unroll
                for (int j = 0; j < 4; j++)
                    ffma2(acc[i][j], ap[i], bp[j]);
        }
        // epilogue: dist + topk insert (all 16B-aligned vector loads)
        const float* sqm = sq + b * NN + m0;
        float4 sqL = *(const float4*)&sqm[mc4];
        float4 sqR = *(const float4*)&sqm[32 + mc4];
        float sv[8] = {sqL.x, sqL.y, sqL.z, sqL.w, sqR.x, sqR.y, sqR.z, sqR.w};
        #pragma unroll
        for (int i = 0; i < 4; i++) {
            const float* rpr = rp + (size_t)(n0 + rbase + i) * NN + m0;
            float4 rL = *(const float4*)&rpr[mc4];
            float4 rR = *(const float4*)&rpr[32 + mc4];
            float rv[8] = {rL.x, rL.y, rL.z, rL.w, rR.x, rR.y, rR.z, rR.w};
            float2 p01 = unpack2(acc[i][0]);
            float2 p23 = unpack2(acc[i][1]);
            float2 p45 = unpack2(acc[i][2]);
            float2 p67 = unpack2(acc[i][3]);
            float dot[8] = {p01.x, p01.y, p23.x, p23.y, p45.x, p45.y, p67.x, p67.y};
            float base = sqn[i];
            #pragma unroll
            for (int j = 0; j < 8; j++) {
                int m = m0 + (j < 4 ? mc4 + j : 32 + mc4 + (j - 4));
                float d = fmaf(-2.f, dot[j], base + sv[j] + rv[j]);
                tk_insert(d, m, tv[i], ti[i], wv[i], wi[i]);
            }
        }
    }

    // ---------- merge: two passes of 32 rows using sh2 ----------
    __syncthreads();
    float* cv = sh2;                          // [32][8][9] values
    int*   ci = (int*)(sh2 + 32 * 8 * KK);    // [32][8][9] indices
    int mc = tid & 7;
    #pragma unroll 1
    for (int pass = 0; pass < 2; pass++) {
        if ((mr >> 3) == pass) {
            int lr = rbase - pass * 32;       // 0..28
            #pragma unroll
            for (int i = 0; i < 4; i++)
                #pragma unroll
                for (int k = 0; k < KK; k++) {
                    cv[((lr + i) * 8 + mc) * KK + k] = tv[i][k];
                    ci[((lr + i) * 8 + mc) * KK + k] = ti[i][k];
                }
        }
        __syncthreads();
        if (tid < 32) {
            float* rv = cv + tid * 8 * KK;
            int*   ri = ci + tid * 8 * KK;
            size_t base = (((size_t)b * NN + n0 + pass * 32 + tid) * 2 + half) * KK;
            for (int k = 0; k < KK; k++) {
                float best = 2e30f; int bi = 0, bt = 0;
                for (int t = 0; t < 8 * KK; t++) {
                    float v = rv[t];
                    if (v < best) { best = v; bi = ri[t]; bt = t; }
                }
                rv[bt] = 3e30f;   // consume
                pv[base + k] = best;
                pi[base + k] = bi;
            }
        }
        __syncthreads();
    }
}

// ---------------- merge partial top-9 halves: 18 -> 9 (tie-break lower index)
__global__ __launch_bounds__(256) void topk_merge_kernel(
    const float* __restrict__ pv, const int* __restrict__ pi,
    int* __restrict__ oidx)
{
    int t = blockIdx.x * 256 + threadIdx.x;
    if (t >= BB * NN) return;
    float lv[2 * KK]; int li[2 * KK];
    const float* v = pv + (size_t)t * 2 * KK;
    const int*   ii = pi + (size_t)t * 2 * KK;
    #pragma unroll
    for (int k = 0; k < 2 * KK; k++) { lv[k] = v[k]; li[k] = ii[k]; }
    int* op = oidx + (size_t)t * KK;
    #pragma unroll
    for (int k = 0; k < KK; k++) {
        float best = 2e30f; int bi = 0, bt = 0;
        #pragma unroll
        for (int c = 0; c < 2 * KK; c++) {
            float vv = lv[c];
            if (vv < best || (vv == best && li[c] < bi)) { best = vv; bi = li[c]; bt = c; }
        }
        lv[bt] = 3e30f;
        op[k] = bi;
    }
}

// ---------------- gather neighbors, max(x_j - x_i), write channel-interleaved (B,2C,N)
__global__ __launch_bounds__(256) void aggregate_kernel(
    const float* __restrict__ xf, const int* __restrict__ idx, float* __restrict__ y)
{
    int bc = blockIdx.x;            // b*CC + c
    __shared__ float row[NN];
    const float* p = xf + (size_t)bc * NN;
    for (int i = threadIdx.x; i < NN; i += 256) row[i] = p[i];
    __syncthreads();
    int b = bc / CC, c = bc - b * CC;
    const int* ip = idx + (size_t)b * NN * KK;
    float* y0 = y + ((size_t)b * C2 + 2 * c) * NN;
    float* y1 = y0 + NN;
    for (int n = threadIdx.x; n < NN; n += 256) {
        float xi = row[n];
        float mx = -3e38f;
        #pragma unroll
        for (int k = 0; k < KK; k++) {
            int j = ip[n * KK + k];
            mx = fmaxf(mx, row[j] - xi);
        }
        y0[n] = xi;
        y1[n] = mx;
    }
}

// ---------------- host orchestration ----------------
static void run_conv(const float* X, const float* W, const float* bias,
                     float* out, int Cout, int Cin)
{
    dim3 g(NN / 64, (Cout + 63) / 64, BB);
    gemm_bias_kernel<<<g, 128>>>(X, W, bias, out, Cout, Cin);
}
static void run_inorm(const float* in, float* out, const float* res, int Crows, int act)
{
    inorm_kernel<<<BB * Crows, 256>>>(in, out, res, act);
}

extern "C" void kernel_launch(void* const* d_in, const int* in_sizes, int n_in,
                              void* d_out, int out_size)
{
    (void)in_sizes; (void)n_in; (void)out_size;
    const float* x  = (const float*)d_in[0];
    const float* rp = (const float*)d_in[1];
    const float* P[20];
    for (int i = 0; i < 20; i++) P[i] = (const float*)d_in[2 + i];

    float *act, *t1, *xf, *xnp, *sqp, *big, *pvp; int *idxp, *pip;
    cudaGetSymbolAddress((void**)&act,  g_act);
    cudaGetSymbolAddress((void**)&t1,   g_t1);
    cudaGetSymbolAddress((void**)&xf,   g_xf);
    cudaGetSymbolAddress((void**)&xnp,  g_xn);
    cudaGetSymbolAddress((void**)&sqp,  g_sq);
    cudaGetSymbolAddress((void**)&idxp, g_idx);
    cudaGetSymbolAddress((void**)&pvp,  g_pv);
    cudaGetSymbolAddress((void**)&pip,  g_pi);
    cudaGetSymbolAddress((void**)&big,  g_big);
    float* y2 = big;                          // (B,2C,N)
    float* t3 = big + (size_t)BB * C2 * NN;   // (B,2C,N)
    float* out = (float*)d_out;

    auto grapher = [&](const float* inx,
                       const float* w1, const float* b1,
                       const float* mw, const float* mb,
                       const float* w2, const float* b2, float* outp) {
        run_conv(inx, w1, b1, t1, CC, CC);
        run_inorm(t1, xf, nullptr, CC, 0);                          // xf
        l2norm_kernel<<<(BB * NN + 255) / 256, 256>>>(xf, xnp, sqp);
        dim3 dg(NN / 64, 2, BB);
        dist_topk_kernel<<<dg, 128>>>(xnp, sqp, rp, pvp, pip);
        topk_merge_kernel<<<(BB * NN + 255) / 256, 256>>>(pvp, pip, idxp);
        aggregate_kernel<<<BB * CC, 256>>>(xf, idxp, y2);           // (B,2C,N)
        run_conv(y2, mw, mb, t3, C2, C2);
        run_inorm(t3, t3, nullptr, C2, 1);                          // gelu, in-place
        run_conv(t3, w2, b2, t1, CC, C2);
        run_inorm(t1, outp, inx, CC, 0);                            // + shortcut
    };
    auto ffn = [&](float* a, const float* w1, const float* b1,
                   const float* w2, const float* b2) {
        run_conv(a, w1, b1, big, C4, CC);
        run_inorm(big, big, nullptr, C4, 1);                        // gelu, in-place
        run_conv(big, w2, b2, t1, CC, C4);
        run_inorm(t1, a, a, CC, 0);                                 // + shortcut
    };

    grapher(x, P[0], P[1], P[2], P[3], P[4], P[5], act);
    ffn(act, P[12], P[13], P[14], P[15]);
    run_inorm(act, act, nullptr, CC, 2);                            // relu(inorm)
    grapher(act, P[6], P[7], P[8], P[9], P[10], P[11], act);
    ffn(act, P[16], P[17], P[18], P[19]);
    run_inorm(act, out, x, CC, 0);                                  // x + inorm(y)
}

// round 10
// speedup vs baseline: 1.4689x; 1.4167x over previous
#include <cuda_runtime.h>
#include <math.h>

static constexpr int BB = 8;
static constexpr int CC = 96;
static constexpr int C2 = 192;
static constexpr int C4 = 384;
static constexpr int NN = 3136;   // 56*56
static constexpr int KK = 9;
static constexpr float EPS_ = 1e-5f;

// ---------------- scratch (no allocations allowed) ----------------
__device__ float g_act[BB * CC * NN];
__device__ float g_t1 [BB * CC * NN];
__device__ float g_xf [BB * CC * NN];
__device__ float g_xn [BB * CC * NN];
__device__ float g_sq [BB * NN];
__device__ int   g_idx[BB * NN * KK];
__device__ float g_big[BB * C4 * NN];   // ffn hidden; also 2C y2 + 2C t3 for grapher

// ---------------- packed f32x2 helpers (FFMA2 via PTX) ----------------
typedef unsigned long long ull;
__device__ __forceinline__ ull pack2(float lo, float hi) {
    ull r;
    asm("mov.b64 %0, {%1, %2};" : "=l"(r) : "f"(lo), "f"(hi));
    return r;
}
__device__ __forceinline__ void ffma2(ull& d, ull a, ull b) {
    asm("fma.rn.f32x2 %0, %1, %2, %3;" : "=l"(d) : "l"(a), "l"(b), "l"(d));
}
__device__ __forceinline__ float2 unpack2(ull v) {
    float2 f;
    asm("mov.b64 {%0, %1}, %2;" : "=f"(f.x), "=f"(f.y) : "l"(v));
    return f;
}

// ---------------- cp.async helpers ----------------
__device__ __forceinline__ void cp16(void* smem, const void* gmem) {
    unsigned s = (unsigned)__cvta_generic_to_shared(smem);
    asm volatile("cp.async.cg.shared.global [%0], [%1], 16;\n" :: "r"(s), "l"(gmem));
}
__device__ __forceinline__ void cp_commit() {
    asm volatile("cp.async.commit_group;\n");
}
__device__ __forceinline__ void cp_wait0() {
    asm volatile("cp.async.wait_group 0;\n");
}

// ---------------- 1x1 conv == batched GEMM: out[b,o,n] = sum_c W[o,c] X[b,c,n] + bias[o]
// 128 threads, 64x64 tile, thread = 4 o-rows x 8 n-cols (4 f32x2 pairs)
__global__ __launch_bounds__(128) void gemm_bias_kernel(
    const float* __restrict__ X, const float* __restrict__ W,
    const float* __restrict__ bias, float* __restrict__ out,
    int Cout, int Cin)
{
    int b  = blockIdx.z;
    int n0 = blockIdx.x * 64;
    int o0 = blockIdx.y * 64;
    int tid = threadIdx.x;
    int ty4 = (tid >> 3) * 4;   // 0..60 step 4
    int tx4 = (tid & 7) * 4;    // 0..28 step 4
    __shared__ float Ws[32][64];   // [k][o]
    __shared__ float Xs[32][64];   // [k][n]
    ull acc[4][4];
    #pragma unroll
    for (int i = 0; i < 4; i++)
        #pragma unroll
        for (int j = 0; j < 4; j++) acc[i][j] = 0ull;
    const float* Xb = X + (size_t)b * Cin * NN;

    for (int kt = 0; kt < Cin; kt += 32) {
        for (int t = tid; t < 512; t += 128) {
            int o = t & 63, kq = t >> 6;
            float4 w = make_float4(0.f, 0.f, 0.f, 0.f);
            if (o0 + o < Cout)
                w = *(const float4*)&W[(size_t)(o0 + o) * Cin + kt + kq * 4];
            Ws[kq * 4 + 0][o] = w.x;
            Ws[kq * 4 + 1][o] = w.y;
            Ws[kq * 4 + 2][o] = w.z;
            Ws[kq * 4 + 3][o] = w.w;
        }
        for (int t = tid; t < 512; t += 128) {
            int k = t >> 4, nq = t & 15;
            *(float4*)&Xs[k][nq * 4] =
                *(const float4*)&Xb[(size_t)(kt + k) * NN + n0 + nq * 4];
        }
        __syncthreads();
        #pragma unroll 8
        for (int k = 0; k < 32; k++) {
            float4 a = *(const float4*)&Ws[k][ty4];           // quarter-warp broadcast
            ulonglong2 bl = *(const ulonglong2*)&Xs[k][tx4];  // free f32x2 pairs
            ulonglong2 br = *(const ulonglong2*)&Xs[k][32 + tx4];
            ull bp[4] = {bl.x, bl.y, br.x, br.y};
            ull ap[4] = {pack2(a.x, a.x), pack2(a.y, a.y),
                         pack2(a.z, a.z), pack2(a.w, a.w)};
            #pragma unroll
            for (int i = 0; i < 4; i++)
                #pragma unroll
                for (int j = 0; j < 4; j++)
                    ffma2(acc[i][j], ap[i], bp[j]);
        }
        __syncthreads();
    }
    #pragma unroll
    for (int i = 0; i < 4; i++) {
        int o = o0 + ty4 + i;
        if (o < Cout) {
            float bvv = bias[o];
            float* op = out + ((size_t)b * Cout + o) * NN + n0;
            float2 p0 = unpack2(acc[i][0]), p1 = unpack2(acc[i][1]);
            float2 p2 = unpack2(acc[i][2]), p3 = unpack2(acc[i][3]);
            *(float4*)&op[tx4] =
                make_float4(p0.x + bvv, p0.y + bvv, p1.x + bvv, p1.y + bvv);
            *(float4*)&op[32 + tx4] =
                make_float4(p2.x + bvv, p2.y + bvv, p3.x + bvv, p3.y + bvv);
        }
    }
}

// ---------------- instance norm per (b,c) row over N; optional act + residual
// act: 0 none, 1 exact gelu, 2 relu
__global__ __launch_bounds__(256) void inorm_kernel(
    const float* __restrict__ in, float* __restrict__ out,
    const float* __restrict__ res, int act)
{
    int row = blockIdx.x;
    const float* p = in + (size_t)row * NN;
    int tid = threadIdx.x;
    float s = 0.f, s2 = 0.f;
    for (int i = tid; i < NN; i += 256) { float v = p[i]; s += v; s2 += v * v; }
    __shared__ float r0s[256], r1s[256];
    r0s[tid] = s; r1s[tid] = s2;
    __syncthreads();
    for (int st = 128; st > 0; st >>= 1) {
        if (tid < st) { r0s[tid] += r0s[tid + st]; r1s[tid] += r1s[tid + st]; }
        __syncthreads();
    }
    __shared__ float msh, rsh;
    if (tid == 0) {
        float mean = r0s[0] * (1.f / NN);
        float var  = r1s[0] * (1.f / NN) - mean * mean;
        msh = mean; rsh = rsqrtf(var + EPS_);
    }
    __syncthreads();
    float mean = msh, rstd = rsh;
    const float* rq = res ? res + (size_t)row * NN : nullptr;
    float* op = out + (size_t)row * NN;
    for (int i = tid; i < NN; i += 256) {
        float v = (p[i] - mean) * rstd;
        if (act == 1) v = 0.5f * v * (1.f + erff(v * 0.70710678118654752f));
        else if (act == 2) v = fmaxf(v, 0.f);
        if (rq) v += rq[i];
        op[i] = v;
    }
}

// ---------------- l2 normalize over channel dim per (b,n); also emit sq = ||xn||^2
__global__ __launch_bounds__(256) void l2norm_kernel(
    const float* __restrict__ xf, float* __restrict__ xn, float* __restrict__ sq)
{
    int t = blockIdx.x * 256 + threadIdx.x;
    if (t >= BB * NN) return;
    int b = t / NN, n = t - b * NN;
    const float* p = xf + (size_t)b * CC * NN + n;
    float s = 0.f;
    #pragma unroll 16
    for (int c = 0; c < CC; c++) { float v = p[(size_t)c * NN]; s += v * v; }
    float inv = 1.f / fmaxf(sqrtf(s), 1e-12f);
    float* q = xn + (size_t)b * CC * NN + n;
    #pragma unroll 16
    for (int c = 0; c < CC; c++) q[(size_t)c * NN] = p[(size_t)c * NN] * inv;
    sq[t] = s * inv * inv;
}

// ---------------- fused pairwise distance + top-9 smallest
// R6 config (128 threads, 64 n-rows, thread = 4 rows x 8 cols, FFMA2)
// + cp.async double-buffered m-tile prefetch (dynamic smem: 24 + 2x24 KB)
__device__ __forceinline__ void tk_insert(float v, int m, float* tv, int* ti,
                                          float& wv, int& wi)
{
    if (v < wv) {
        tv[wi] = v; ti[wi] = m;
        wv = tv[0]; wi = 0;
        #pragma unroll
        for (int k = 1; k < KK; k++) if (tv[k] > wv) { wv = tv[k]; wi = k; }
    }
}

__global__ __launch_bounds__(128) void dist_topk_kernel(
    const float* __restrict__ xn, const float* __restrict__ sq,
    const float* __restrict__ rp, int* __restrict__ oidx)
{
    extern __shared__ float dsm[];
    float* Xn_s = dsm;                  // CC*64 = 24 KB
    float* buf0 = dsm + CC * 64;        // 24 KB
    float* buf1 = dsm + CC * 64 * 2;    // 24 KB

    int b = blockIdx.y;
    int n0 = blockIdx.x * 64;
    int tid = threadIdx.x;
    int mr  = tid >> 3;        // 0..15
    int mc4 = (tid & 7) * 4;   // 0..28
    int rbase = mr * 4;        // rows rbase..rbase+3 (0..63)

    const float* xb = xn + (size_t)b * CC * NN;
    // prologue: async-load Xn tile + m-tile 0, one group
    for (int t = tid; t < CC * 16; t += 128) {
        int c = t >> 4, q = (t & 15) * 4;
        cp16(&Xn_s[c * 64 + q], &xb[(size_t)c * NN + n0 + q]);
    }
    for (int t = tid; t < CC * 16; t += 128) {
        int c = t >> 4, q = (t & 15) * 4;
        cp16(&buf0[c * 64 + q], &xb[(size_t)c * NN + q]);
    }
    cp_commit();

    float4 sqn4 = *(const float4*)&sq[b * NN + n0 + rbase];
    float sqn[4] = {sqn4.x, sqn4.y, sqn4.z, sqn4.w};

    float tv[4][KK]; int ti[4][KK];
    float wv[4]; int wi[4];
    #pragma unroll
    for (int i = 0; i < 4; i++) {
        #pragma unroll
        for (int k = 0; k < KK; k++) { tv[i][k] = 1e30f; ti[i][k] = 0; }
        wv[i] = 1e30f; wi[i] = 0;
    }

    constexpr int T = NN / 64;   // 49 tiles
    for (int t = 0; t < T; t++) {
        cp_wait0();
        __syncthreads();
        float* cur = (t & 1) ? buf1 : buf0;
        if (t + 1 < T) {
            float* nxt = (t & 1) ? buf0 : buf1;
            int mnext = (t + 1) * 64;
            for (int u = tid; u < CC * 16; u += 128) {
                int c = u >> 4, q = (u & 15) * 4;
                cp16(&nxt[c * 64 + q], &xb[(size_t)c * NN + mnext + q]);
            }
            cp_commit();
        }
        int m0 = t * 64;
        ull acc[4][4];
        #pragma unroll
        for (int i = 0; i < 4; i++)
            #pragma unroll
            for (int j = 0; j < 4; j++) acc[i][j] = 0ull;
        #pragma unroll 4
        for (int c = 0; c < CC; c++) {
            float4 a = *(const float4*)&Xn_s[c * 64 + rbase];           // broadcast
            ulonglong2 blp = *(const ulonglong2*)&cur[c * 64 + mc4];    // free pairs
            ulonglong2 brp = *(const ulonglong2*)&cur[c * 64 + 32 + mc4];
            ull bp[4] = {blp.x, blp.y, brp.x, brp.y};
            ull ap[4] = {pack2(a.x, a.x), pack2(a.y, a.y),
                         pack2(a.z, a.z), pack2(a.w, a.w)};
            #pragma unroll
            for (int i = 0; i < 4; i++)
                #pragma unroll
                for (int j = 0; j < 4; j++)
                    ffma2(acc[i][j], ap[i], bp[j]);
        }
        // epilogue: dist + topk insert (all 16B-aligned vector loads)
        const float* sqm = sq + b * NN + m0;
        float4 sqL = *(const float4*)&sqm[mc4];
        float4 sqR = *(const float4*)&sqm[32 + mc4];
        float sv[8] = {sqL.x, sqL.y, sqL.z, sqL.w, sqR.x, sqR.y, sqR.z, sqR.w};
        #pragma unroll
        for (int i = 0; i < 4; i++) {
            const float* rpr = rp + (size_t)(n0 + rbase + i) * NN + m0;
            float4 rL = *(const float4*)&rpr[mc4];
            float4 rR = *(const float4*)&rpr[32 + mc4];
            float rv[8] = {rL.x, rL.y, rL.z, rL.w, rR.x, rR.y, rR.z, rR.w};
            float2 p01 = unpack2(acc[i][0]);
            float2 p23 = unpack2(acc[i][1]);
            float2 p45 = unpack2(acc[i][2]);
            float2 p67 = unpack2(acc[i][3]);
            float dot[8] = {p01.x, p01.y, p23.x, p23.y, p45.x, p45.y, p67.x, p67.y};
            float base = sqn[i];
            #pragma unroll
            for (int j = 0; j < 8; j++) {
                int m = m0 + (j < 4 ? mc4 + j : 32 + mc4 + (j - 4));
                float d = fmaf(-2.f, dot[j], base + sv[j] + rv[j]);
                tk_insert(d, m, tv[i], ti[i], wv[i], wi[i]);
            }
        }
    }

    // ---------- merge: two passes of 32 rows, reuse Xn_s (done) ----------
    __syncthreads();
    float* cv = Xn_s;                          // [32][8][9] values (2304 floats)
    int*   ci = (int*)(Xn_s + 32 * 8 * KK);    // [32][8][9] indices
    int mc = tid & 7;
    #pragma unroll 1
    for (int pass = 0; pass < 2; pass++) {
        if ((mr >> 3) == pass) {
            int lr = rbase - pass * 32;       // 0..28
            #pragma unroll
            for (int i = 0; i < 4; i++)
                #pragma unroll
                for (int k = 0; k < KK; k++) {
                    cv[((lr + i) * 8 + mc) * KK + k] = tv[i][k];
                    ci[((lr + i) * 8 + mc) * KK + k] = ti[i][k];
                }
        }
        __syncthreads();
        if (tid < 32) {
            float* rv = cv + tid * 8 * KK;
            int*   ri = ci + tid * 8 * KK;
            int* op = oidx + ((size_t)b * NN + n0 + pass * 32 + tid) * KK;
            for (int k = 0; k < KK; k++) {
                float best = 2e30f; int bi = 0, bt = 0;
                for (int t = 0; t < 8 * KK; t++) {
                    float v = rv[t];
                    if (v < best) { best = v; bi = ri[t]; bt = t; }
                }
                rv[bt] = 3e30f;   // consume
                op[k] = bi;
            }
        }
        __syncthreads();
    }
}

// ---------------- gather neighbors, max(x_j - x_i), write channel-interleaved (B,2C,N)
__global__ __launch_bounds__(256) void aggregate_kernel(
    const float* __restrict__ xf, const int* __restrict__ idx, float* __restrict__ y)
{
    int bc = blockIdx.x;            // b*CC + c
    __shared__ float row[NN];
    const float* p = xf + (size_t)bc * NN;
    for (int i = threadIdx.x; i < NN; i += 256) row[i] = p[i];
    __syncthreads();
    int b = bc / CC, c = bc - b * CC;
    const int* ip = idx + (size_t)b * NN * KK;
    float* y0 = y + ((size_t)b * C2 + 2 * c) * NN;
    float* y1 = y0 + NN;
    for (int n = threadIdx.x; n < NN; n += 256) {
        float xi = row[n];
        float mx = -3e38f;
        #pragma unroll
        for (int k = 0; k < KK; k++) {
            int j = ip[n * KK + k];
            mx = fmaxf(mx, row[j] - xi);
        }
        y0[n] = xi;
        y1[n] = mx;
    }
}

// ---------------- host orchestration ----------------
static constexpr int DIST_SMEM = CC * 64 * 3 * (int)sizeof(float);   // 73728 B

static void run_conv(const float* X, const float* W, const float* bias,
                     float* out, int Cout, int Cin)
{
    dim3 g(NN / 64, (Cout + 63) / 64, BB);
    gemm_bias_kernel<<<g, 128>>>(X, W, bias, out, Cout, Cin);
}
static void run_inorm(const float* in, float* out, const float* res, int Crows, int act)
{
    inorm_kernel<<<BB * Crows, 256>>>(in, out, res, act);
}

extern "C" void kernel_launch(void* const* d_in, const int* in_sizes, int n_in,
                              void* d_out, int out_size)
{
    (void)in_sizes; (void)n_in; (void)out_size;
    const float* x  = (const float*)d_in[0];
    const float* rp = (const float*)d_in[1];
    const float* P[20];
    for (int i = 0; i < 20; i++) P[i] = (const float*)d_in[2 + i];

    cudaFuncSetAttribute(dist_topk_kernel,
                         cudaFuncAttributeMaxDynamicSharedMemorySize, DIST_SMEM);

    float *act, *t1, *xf, *xnp, *sqp, *big; int* idxp;
    cudaGetSymbolAddress((void**)&act,  g_act);
    cudaGetSymbolAddress((void**)&t1,   g_t1);
    cudaGetSymbolAddress((void**)&xf,   g_xf);
    cudaGetSymbolAddress((void**)&xnp,  g_xn);
    cudaGetSymbolAddress((void**)&sqp,  g_sq);
    cudaGetSymbolAddress((void**)&idxp, g_idx);
    cudaGetSymbolAddress((void**)&big,  g_big);
    float* y2 = big;                          // (B,2C,N)
    float* t3 = big + (size_t)BB * C2 * NN;   // (B,2C,N)
    float* out = (float*)d_out;

    auto grapher = [&](const float* inx,
                       const float* w1, const float* b1,
                       const float* mw, const float* mb,
                       const float* w2, const float* b2, float* outp) {
        run_conv(inx, w1, b1, t1, CC, CC);
        run_inorm(t1, xf, nullptr, CC, 0);                          // xf
        l2norm_kernel<<<(BB * NN + 255) / 256, 256>>>(xf, xnp, sqp);
        dim3 dg(NN / 64, BB);
        dist_topk_kernel<<<dg, 128, DIST_SMEM>>>(xnp, sqp, rp, idxp);
        aggregate_kernel<<<BB * CC, 256>>>(xf, idxp, y2);           // (B,2C,N)
        run_conv(y2, mw, mb, t3, C2, C2);
        run_inorm(t3, t3, nullptr, C2, 1);                          // gelu, in-place
        run_conv(t3, w2, b2, t1, CC, C2);
        run_inorm(t1, outp, inx, CC, 0);                            // + shortcut
    };
    auto ffn = [&](float* a, const float* w1, const float* b1,
                   const float* w2, const float* b2) {
        run_conv(a, w1, b1, big, C4, CC);
        run_inorm(big, big, nullptr, C4, 1);                        // gelu, in-place
        run_conv(big, w2, b2, t1, CC, C4);
        run_inorm(t1, a, a, CC, 0);                                 // + shortcut
    };

    grapher(x, P[0], P[1], P[2], P[3], P[4], P[5], act);
    ffn(act, P[12], P[13], P[14], P[15]);
    run_inorm(act, act, nullptr, CC, 2);                            // relu(inorm)
    grapher(act, P[6], P[7], P[8], P[9], P[10], P[11], act);
    ffn(act, P[16], P[17], P[18], P[19]);
    run_inorm(act, out, x, CC, 0);                                  // x + inorm(y)
}

// round 11
// speedup vs baseline: 1.6745x; 1.1399x over previous
#include <cuda_runtime.h>
#include <math.h>

static constexpr int BB = 8;
static constexpr int CC = 96;
static constexpr int C2 = 192;
static constexpr int C4 = 384;
static constexpr int NN = 3136;   // 56*56
static constexpr int KK = 9;
static constexpr float EPS_ = 1e-5f;

// ---------------- scratch (no allocations allowed) ----------------
__device__ float g_act[BB * CC * NN];
__device__ float g_t1 [BB * CC * NN];
__device__ float g_xf [BB * CC * NN];
__device__ float g_xn [BB * CC * NN];
__device__ float g_sq [BB * NN];
__device__ int   g_idx[BB * NN * KK];
__device__ float g_big[BB * C4 * NN];   // ffn hidden; also 2C y2 + 2C t3 for grapher

// ---------------- packed f32x2 helpers (FFMA2 via PTX) ----------------
typedef unsigned long long ull;
__device__ __forceinline__ ull pack2(float lo, float hi) {
    ull r;
    asm("mov.b64 %0, {%1, %2};" : "=l"(r) : "f"(lo), "f"(hi));
    return r;
}
__device__ __forceinline__ void ffma2(ull& d, ull a, ull b) {
    asm("fma.rn.f32x2 %0, %1, %2, %3;" : "=l"(d) : "l"(a), "l"(b), "l"(d));
}
__device__ __forceinline__ float2 unpack2(ull v) {
    float2 f;
    asm("mov.b64 {%0, %1}, %2;" : "=f"(f.x), "=f"(f.y) : "l"(v));
    return f;
}

// ---------------- 1x1 conv == batched GEMM: out[b,o,n] = sum_c W[o,c] X[b,c,n] + bias[o]
// 128 threads, 64x64 tile, thread = 4 o-rows x 8 n-cols (4 f32x2 pairs)
__global__ __launch_bounds__(128) void gemm_bias_kernel(
    const float* __restrict__ X, const float* __restrict__ W,
    const float* __restrict__ bias, float* __restrict__ out,
    int Cout, int Cin)
{
    int b  = blockIdx.z;
    int n0 = blockIdx.x * 64;
    int o0 = blockIdx.y * 64;
    int tid = threadIdx.x;
    int ty4 = (tid >> 3) * 4;   // 0..60 step 4
    int tx4 = (tid & 7) * 4;    // 0..28 step 4
    __shared__ float Ws[32][64];   // [k][o]
    __shared__ float Xs[32][64];   // [k][n]
    ull acc[4][4];
    #pragma unroll
    for (int i = 0; i < 4; i++)
        #pragma unroll
        for (int j = 0; j < 4; j++) acc[i][j] = 0ull;
    const float* Xb = X + (size_t)b * Cin * NN;

    for (int kt = 0; kt < Cin; kt += 32) {
        for (int t = tid; t < 512; t += 128) {
            int o = t & 63, kq = t >> 6;
            float4 w = make_float4(0.f, 0.f, 0.f, 0.f);
            if (o0 + o < Cout)
                w = *(const float4*)&W[(size_t)(o0 + o) * Cin + kt + kq * 4];
            Ws[kq * 4 + 0][o] = w.x;
            Ws[kq * 4 + 1][o] = w.y;
            Ws[kq * 4 + 2][o] = w.z;
            Ws[kq * 4 + 3][o] = w.w;
        }
        for (int t = tid; t < 512; t += 128) {
            int k = t >> 4, nq = t & 15;
            *(float4*)&Xs[k][nq * 4] =
                *(const float4*)&Xb[(size_t)(kt + k) * NN + n0 + nq * 4];
        }
        __syncthreads();
        #pragma unroll 8
        for (int k = 0; k < 32; k++) {
            float4 a = *(const float4*)&Ws[k][ty4];           // quarter-warp broadcast
            ulonglong2 bl = *(const ulonglong2*)&Xs[k][tx4];  // free f32x2 pairs
            ulonglong2 br = *(const ulonglong2*)&Xs[k][32 + tx4];
            ull bp[4] = {bl.x, bl.y, br.x, br.y};
            ull ap[4] = {pack2(a.x, a.x), pack2(a.y, a.y),
                         pack2(a.z, a.z), pack2(a.w, a.w)};
            #pragma unroll
            for (int i = 0; i < 4; i++)
                #pragma unroll
                for (int j = 0; j < 4; j++)
                    ffma2(acc[i][j], ap[i], bp[j]);
        }
        __syncthreads();
    }
    #pragma unroll
    for (int i = 0; i < 4; i++) {
        int o = o0 + ty4 + i;
        if (o < Cout) {
            float bvv = bias[o];
            float* op = out + ((size_t)b * Cout + o) * NN + n0;
            float2 p0 = unpack2(acc[i][0]), p1 = unpack2(acc[i][1]);
            float2 p2 = unpack2(acc[i][2]), p3 = unpack2(acc[i][3]);
            *(float4*)&op[tx4] =
                make_float4(p0.x + bvv, p0.y + bvv, p1.x + bvv, p1.y + bvv);
            *(float4*)&op[32 + tx4] =
                make_float4(p2.x + bvv, p2.y + bvv, p3.x + bvv, p3.y + bvv);
        }
    }
}

// ---------------- instance norm per (b,c) row over N; optional act + residual
// act: 0 none, 1 exact gelu, 2 relu
__global__ __launch_bounds__(256) void inorm_kernel(
    const float* __restrict__ in, float* __restrict__ out,
    const float* __restrict__ res, int act)
{
    int row = blockIdx.x;
    const float* p = in + (size_t)row * NN;
    int tid = threadIdx.x;
    float s = 0.f, s2 = 0.f;
    for (int i = tid; i < NN; i += 256) { float v = p[i]; s += v; s2 += v * v; }
    __shared__ float r0s[256], r1s[256];
    r0s[tid] = s; r1s[tid] = s2;
    __syncthreads();
    for (int st = 128; st > 0; st >>= 1) {
        if (tid < st) { r0s[tid] += r0s[tid + st]; r1s[tid] += r1s[tid + st]; }
        __syncthreads();
    }
    __shared__ float msh, rsh;
    if (tid == 0) {
        float mean = r0s[0] * (1.f / NN);
        float var  = r1s[0] * (1.f / NN) - mean * mean;
        msh = mean; rsh = rsqrtf(var + EPS_);
    }
    __syncthreads();
    float mean = msh, rstd = rsh;
    const float* rq = res ? res + (size_t)row * NN : nullptr;
    float* op = out + (size_t)row * NN;
    for (int i = tid; i < NN; i += 256) {
        float v = (p[i] - mean) * rstd;
        if (act == 1) v = 0.5f * v * (1.f + erff(v * 0.70710678118654752f));
        else if (act == 2) v = fmaxf(v, 0.f);
        if (rq) v += rq[i];
        op[i] = v;
    }
}

// ---------------- l2 normalize over channel dim per (b,n); also emit sq = ||xn||^2
__global__ __launch_bounds__(256) void l2norm_kernel(
    const float* __restrict__ xf, float* __restrict__ xn, float* __restrict__ sq)
{
    int t = blockIdx.x * 256 + threadIdx.x;
    if (t >= BB * NN) return;
    int b = t / NN, n = t - b * NN;
    const float* p = xf + (size_t)b * CC * NN + n;
    float s = 0.f;
    #pragma unroll 16
    for (int c = 0; c < CC; c++) { float v = p[(size_t)c * NN]; s += v * v; }
    float inv = 1.f / fmaxf(sqrtf(s), 1e-12f);
    float* q = xn + (size_t)b * CC * NN + n;
    #pragma unroll 16
    for (int c = 0; c < CC; c++) q[(size_t)c * NN] = p[(size_t)c * NN] * inv;
    sq[t] = s * inv * inv;
}

// ---------------- fused pairwise distance + top-9 smallest
// 256 threads, 64 n-rows per block, m-tiles of 64
// thread = 4 n-rows x 4 m-cols: a = LDS.128 (2-line bcast/warp),
// b = 1 LDS.128 (lanes i, i+16 dedup); 8 FFMA2 per c per thread.
__device__ __forceinline__ void tk_insert(float v, int m, float* tv, int* ti,
                                          float& wv, int& wi)
{
    if (v < wv) {
        tv[wi] = v; ti[wi] = m;
        wv = tv[0]; wi = 0;
        #pragma unroll
        for (int k = 1; k < KK; k++) if (tv[k] > wv) { wv = tv[k]; wi = k; }
    }
}

__global__ __launch_bounds__(256) void dist_topk_kernel(
    const float* __restrict__ xn, const float* __restrict__ sq,
    const float* __restrict__ rp, int* __restrict__ oidx)
{
    __shared__ float smem_all[CC * 64 * 2];   // 48 KB
    float* Xn_s = smem_all;            // [c][64 n-rows]
    float* sh2  = smem_all + CC * 64;  // [c][64 m]; reused for merge

    int b = blockIdx.y;
    int n0 = blockIdx.x * 64;
    int tid = threadIdx.x;
    int g   = tid >> 4;          // 0..15 row group
    int mc4 = (tid & 15) * 4;    // 0..60 col group
    int rbase = g * 4;           // rows rbase..rbase+3

    const float* xb = xn + (size_t)b * CC * NN;
    for (int t = tid; t < CC * 16; t += 256) {
        int c = t >> 4, q = (t & 15) * 4;
        *(float4*)&Xn_s[c * 64 + q] = *(const float4*)&xb[(size_t)c * NN + n0 + q];
    }
    __syncthreads();

    float4 sqn4 = *(const float4*)&sq[b * NN + n0 + rbase];
    float sqn[4] = {sqn4.x, sqn4.y, sqn4.z, sqn4.w};

    float tv[4][KK]; int ti[4][KK];
    float wv[4]; int wi[4];
    #pragma unroll
    for (int i = 0; i < 4; i++) {
        #pragma unroll
        for (int k = 0; k < KK; k++) { tv[i][k] = 1e30f; ti[i][k] = 0; }
        wv[i] = 1e30f; wi[i] = 0;
    }

    for (int m0 = 0; m0 < NN; m0 += 64) {
        __syncthreads();
        for (int t = tid; t < CC * 16; t += 256) {
            int c = t >> 4, q = (t & 15) * 4;
            *(float4*)&sh2[c * 64 + q] = *(const float4*)&xb[(size_t)c * NN + m0 + q];
        }
        __syncthreads();
        ull acc[4][2];
        #pragma unroll
        for (int i = 0; i < 4; i++) { acc[i][0] = 0ull; acc[i][1] = 0ull; }
        #pragma unroll 8
        for (int c = 0; c < CC; c++) {
            float4 a = *(const float4*)&Xn_s[c * 64 + rbase];         // broadcast
            ulonglong2 bq = *(const ulonglong2*)&sh2[c * 64 + mc4];   // 2 f32x2 pairs
            ull ap[4] = {pack2(a.x, a.x), pack2(a.y, a.y),
                         pack2(a.z, a.z), pack2(a.w, a.w)};
            #pragma unroll
            for (int i = 0; i < 4; i++) {
                ffma2(acc[i][0], ap[i], bq.x);
                ffma2(acc[i][1], ap[i], bq.y);
            }
        }
        // epilogue: dist + topk insert (all 16B-aligned vector loads)
        float4 sq4 = *(const float4*)&sq[b * NN + m0 + mc4];
        float sv[4] = {sq4.x, sq4.y, sq4.z, sq4.w};
        #pragma unroll
        for (int i = 0; i < 4; i++) {
            float4 r4 = *(const float4*)&rp[(size_t)(n0 + rbase + i) * NN + m0 + mc4];
            float rv[4] = {r4.x, r4.y, r4.z, r4.w};
            float2 p01 = unpack2(acc[i][0]);
            float2 p23 = unpack2(acc[i][1]);
            float dot[4] = {p01.x, p01.y, p23.x, p23.y};
            float base = sqn[i];
            #pragma unroll
            for (int j = 0; j < 4; j++) {
                int m = m0 + mc4 + j;
                float d = fmaf(-2.f, dot[j], base + sv[j] + rv[j]);
                tk_insert(d, m, tv[i], ti[i], wv[i], wi[i]);
            }
        }
    }

    // ---------- merge: two passes of 32 rows, 16 col-groups each ----------
    __syncthreads();
    float* cv = smem_all;                             // [32][16][9] values (4608 f)
    int*   ci = (int*)(smem_all + 32 * 16 * KK);      // [32][16][9] indices
    int cg = tid & 15;
    #pragma unroll 1
    for (int pass = 0; pass < 2; pass++) {
        if ((g >> 3) == pass) {
            int lr = rbase - pass * 32;               // 0..28
            #pragma unroll
            for (int i = 0; i < 4; i++)
                #pragma unroll
                for (int k = 0; k < KK; k++) {
                    cv[((lr + i) * 16 + cg) * KK + k] = tv[i][k];
                    ci[((lr + i) * 16 + cg) * KK + k] = ti[i][k];
                }
        }
        __syncthreads();
        if (tid < 32) {
            float* rv = cv + tid * 16 * KK;
            int*   ri = ci + tid * 16 * KK;
            int* op = oidx + ((size_t)b * NN + n0 + pass * 32 + tid) * KK;
            for (int k = 0; k < KK; k++) {
                float best = 2e30f; int bi = 0, bt = 0;
                for (int t = 0; t < 16 * KK; t++) {
                    float v = rv[t];
                    if (v < best) { best = v; bi = ri[t]; bt = t; }
                }
                rv[bt] = 3e30f;   // consume
                op[k] = bi;
            }
        }
        __syncthreads();
    }
}

// ---------------- gather neighbors, max(x_j - x_i), write channel-interleaved (B,2C,N)
__global__ __launch_bounds__(256) void aggregate_kernel(
    const float* __restrict__ xf, const int* __restrict__ idx, float* __restrict__ y)
{
    int bc = blockIdx.x;            // b*CC + c
    __shared__ float row[NN];
    const float* p = xf + (size_t)bc * NN;
    for (int i = threadIdx.x; i < NN; i += 256) row[i] = p[i];
    __syncthreads();
    int b = bc / CC, c = bc - b * CC;
    const int* ip = idx + (size_t)b * NN * KK;
    float* y0 = y + ((size_t)b * C2 + 2 * c) * NN;
    float* y1 = y0 + NN;
    for (int n = threadIdx.x; n < NN; n += 256) {
        float xi = row[n];
        float mx = -3e38f;
        #pragma unroll
        for (int k = 0; k < KK; k++) {
            int j = ip[n * KK + k];
            mx = fmaxf(mx, row[j] - xi);
        }
        y0[n] = xi;
        y1[n] = mx;
    }
}

// ---------------- host orchestration ----------------
static void run_conv(const float* X, const float* W, const float* bias,
                     float* out, int Cout, int Cin)
{
    dim3 g(NN / 64, (Cout + 63) / 64, BB);
    gemm_bias_kernel<<<g, 128>>>(X, W, bias, out, Cout, Cin);
}
static void run_inorm(const float* in, float* out, const float* res, int Crows, int act)
{
    inorm_kernel<<<BB * Crows, 256>>>(in, out, res, act);
}

extern "C" void kernel_launch(void* const* d_in, const int* in_sizes, int n_in,
                              void* d_out, int out_size)
{
    (void)in_sizes; (void)n_in; (void)out_size;
    const float* x  = (const float*)d_in[0];
    const float* rp = (const float*)d_in[1];
    const float* P[20];
    for (int i = 0; i < 20; i++) P[i] = (const float*)d_in[2 + i];

    float *act, *t1, *xf, *xnp, *sqp, *big; int* idxp;
    cudaGetSymbolAddress((void**)&act,  g_act);
    cudaGetSymbolAddress((void**)&t1,   g_t1);
    cudaGetSymbolAddress((void**)&xf,   g_xf);
    cudaGetSymbolAddress((void**)&xnp,  g_xn);
    cudaGetSymbolAddress((void**)&sqp,  g_sq);
    cudaGetSymbolAddress((void**)&idxp, g_idx);
    cudaGetSymbolAddress((void**)&big,  g_big);
    float* y2 = big;                          // (B,2C,N)
    float* t3 = big + (size_t)BB * C2 * NN;   // (B,2C,N)
    float* out = (float*)d_out;

    auto grapher = [&](const float* inx,
                       const float* w1, const float* b1,
                       const float* mw, const float* mb,
                       const float* w2, const float* b2, float* outp) {
        run_conv(inx, w1, b1, t1, CC, CC);
        run_inorm(t1, xf, nullptr, CC, 0);                          // xf
        l2norm_kernel<<<(BB * NN + 255) / 256, 256>>>(xf, xnp, sqp);
        dim3 dg(NN / 64, BB);
        dist_topk_kernel<<<dg, 256>>>(xnp, sqp, rp, idxp);
        aggregate_kernel<<<BB * CC, 256>>>(xf, idxp, y2);           // (B,2C,N)
        run_conv(y2, mw, mb, t3, C2, C2);
        run_inorm(t3, t3, nullptr, C2, 1);                          // gelu, in-place
        run_conv(t3, w2, b2, t1, CC, C2);
        run_inorm(t1, outp, inx, CC, 0);                            // + shortcut
    };
    auto ffn = [&](float* a, const float* w1, const float* b1,
                   const float* w2, const float* b2) {
        run_conv(a, w1, b1, big, C4, CC);
        run_inorm(big, big, nullptr, C4, 1);                        // gelu, in-place
        run_conv(big, w2, b2, t1, CC, C4);
        run_inorm(t1, a, a, CC, 0);                                 // + shortcut
    };

    grapher(x, P[0], P[1], P[2], P[3], P[4], P[5], act);
    ffn(act, P[12], P[13], P[14], P[15]);
    run_inorm(act, act, nullptr, CC, 2);                            // relu(inorm)
    grapher(act, P[6], P[7], P[8], P[9], P[10], P[11], act);
    ffn(act, P[16], P[17], P[18], P[19]);
    run_inorm(act, out, x, CC, 0);                                  // x + inorm(y)
}

// round 12
// speedup vs baseline: 1.6929x; 1.0110x over previous
#include <cuda_runtime.h>
#include <math.h>

static constexpr int BB = 8;
static constexpr int CC = 96;
static constexpr int C2 = 192;
static constexpr int C4 = 384;
static constexpr int NN = 3136;   // 56*56
static constexpr int KK = 9;
static constexpr float EPS_ = 1e-5f;

// ---------------- scratch (no allocations allowed) ----------------
__device__ float g_act[BB * CC * NN];
__device__ float g_t1 [BB * CC * NN];
__device__ float g_xf [BB * CC * NN];
__device__ float g_xn [BB * CC * NN];
__device__ float g_sq [BB * NN];
__device__ int   g_idx[BB * NN * KK];
__device__ float g_big[BB * C4 * NN];   // ffn hidden; also 2C y2 + 2C t3 for grapher

// ---------------- packed f32x2 helpers (FFMA2 via PTX) ----------------
typedef unsigned long long ull;
__device__ __forceinline__ ull pack2(float lo, float hi) {
    ull r;
    asm("mov.b64 %0, {%1, %2};" : "=l"(r) : "f"(lo), "f"(hi));
    return r;
}
__device__ __forceinline__ void ffma2(ull& d, ull a, ull b) {
    asm("fma.rn.f32x2 %0, %1, %2, %3;" : "=l"(d) : "l"(a), "l"(b), "l"(d));
}
__device__ __forceinline__ float2 unpack2(ull v) {
    float2 f;
    asm("mov.b64 {%0, %1}, %2;" : "=f"(f.x), "=f"(f.y) : "l"(v));
    return f;
}

// ---------------- 1x1 conv == batched GEMM: out[b,o,n] = sum_c W[o,c] X[b,c,n] + bias[o]
// 128 threads, 64x64 tile, thread = 4 o-rows x 8 n-cols (4 f32x2 pairs)
__global__ __launch_bounds__(128) void gemm_bias_kernel(
    const float* __restrict__ X, const float* __restrict__ W,
    const float* __restrict__ bias, float* __restrict__ out,
    int Cout, int Cin)
{
    int b  = blockIdx.z;
    int n0 = blockIdx.x * 64;
    int o0 = blockIdx.y * 64;
    int tid = threadIdx.x;
    int ty4 = (tid >> 3) * 4;   // 0..60 step 4
    int tx4 = (tid & 7) * 4;    // 0..28 step 4
    __shared__ float Ws[32][64];   // [k][o]
    __shared__ float Xs[32][64];   // [k][n]
    ull acc[4][4];
    #pragma unroll
    for (int i = 0; i < 4; i++)
        #pragma unroll
        for (int j = 0; j < 4; j++) acc[i][j] = 0ull;
    const float* Xb = X + (size_t)b * Cin * NN;

    for (int kt = 0; kt < Cin; kt += 32) {
        for (int t = tid; t < 512; t += 128) {
            int o = t & 63, kq = t >> 6;
            float4 w = make_float4(0.f, 0.f, 0.f, 0.f);
            if (o0 + o < Cout)
                w = *(const float4*)&W[(size_t)(o0 + o) * Cin + kt + kq * 4];
            Ws[kq * 4 + 0][o] = w.x;
            Ws[kq * 4 + 1][o] = w.y;
            Ws[kq * 4 + 2][o] = w.z;
            Ws[kq * 4 + 3][o] = w.w;
        }
        for (int t = tid; t < 512; t += 128) {
            int k = t >> 4, nq = t & 15;
            *(float4*)&Xs[k][nq * 4] =
                *(const float4*)&Xb[(size_t)(kt + k) * NN + n0 + nq * 4];
        }
        __syncthreads();
        #pragma unroll 8
        for (int k = 0; k < 32; k++) {
            float4 a = *(const float4*)&Ws[k][ty4];           // quarter-warp broadcast
            ulonglong2 bl = *(const ulonglong2*)&Xs[k][tx4];  // free f32x2 pairs
            ulonglong2 br = *(const ulonglong2*)&Xs[k][32 + tx4];
            ull bp[4] = {bl.x, bl.y, br.x, br.y};
            ull ap[4] = {pack2(a.x, a.x), pack2(a.y, a.y),
                         pack2(a.z, a.z), pack2(a.w, a.w)};
            #pragma unroll
            for (int i = 0; i < 4; i++)
                #pragma unroll
                for (int j = 0; j < 4; j++)
                    ffma2(acc[i][j], ap[i], bp[j]);
        }
        __syncthreads();
    }
    #pragma unroll
    for (int i = 0; i < 4; i++) {
        int o = o0 + ty4 + i;
        if (o < Cout) {
            float bvv = bias[o];
            float* op = out + ((size_t)b * Cout + o) * NN + n0;
            float2 p0 = unpack2(acc[i][0]), p1 = unpack2(acc[i][1]);
            float2 p2 = unpack2(acc[i][2]), p3 = unpack2(acc[i][3]);
            *(float4*)&op[tx4] =
                make_float4(p0.x + bvv, p0.y + bvv, p1.x + bvv, p1.y + bvv);
            *(float4*)&op[32 + tx4] =
                make_float4(p2.x + bvv, p2.y + bvv, p3.x + bvv, p3.y + bvv);
        }
    }
}

// ---------------- instance norm per (b,c) row over N; optional act + residual
// act: 0 none, 1 exact gelu, 2 relu
__global__ __launch_bounds__(256) void inorm_kernel(
    const float* __restrict__ in, float* __restrict__ out,
    const float* __restrict__ res, int act)
{
    int row = blockIdx.x;
    const float* p = in + (size_t)row * NN;
    int tid = threadIdx.x;
    float s = 0.f, s2 = 0.f;
    for (int i = tid; i < NN; i += 256) { float v = p[i]; s += v; s2 += v * v; }
    __shared__ float r0s[256], r1s[256];
    r0s[tid] = s; r1s[tid] = s2;
    __syncthreads();
    for (int st = 128; st > 0; st >>= 1) {
        if (tid < st) { r0s[tid] += r0s[tid + st]; r1s[tid] += r1s[tid + st]; }
        __syncthreads();
    }
    __shared__ float msh, rsh;
    if (tid == 0) {
        float mean = r0s[0] * (1.f / NN);
        float var  = r1s[0] * (1.f / NN) - mean * mean;
        msh = mean; rsh = rsqrtf(var + EPS_);
    }
    __syncthreads();
    float mean = msh, rstd = rsh;
    const float* rq = res ? res + (size_t)row * NN : nullptr;
    float* op = out + (size_t)row * NN;
    for (int i = tid; i < NN; i += 256) {
        float v = (p[i] - mean) * rstd;
        if (act == 1) v = 0.5f * v * (1.f + erff(v * 0.70710678118654752f));
        else if (act == 2) v = fmaxf(v, 0.f);
        if (rq) v += rq[i];
        op[i] = v;
    }
}

// ---------------- l2 normalize over channel dim per (b,n); also emit sq = ||xn||^2
__global__ __launch_bounds__(256) void l2norm_kernel(
    const float* __restrict__ xf, float* __restrict__ xn, float* __restrict__ sq)
{
    int t = blockIdx.x * 256 + threadIdx.x;
    if (t >= BB * NN) return;
    int b = t / NN, n = t - b * NN;
    const float* p = xf + (size_t)b * CC * NN + n;
    float s = 0.f;
    #pragma unroll 16
    for (int c = 0; c < CC; c++) { float v = p[(size_t)c * NN]; s += v * v; }
    float inv = 1.f / fmaxf(sqrtf(s), 1e-12f);
    float* q = xn + (size_t)b * CC * NN + n;
    #pragma unroll 16
    for (int c = 0; c < CC; c++) q[(size_t)c * NN] = p[(size_t)c * NN] * inv;
    sq[t] = s * inv * inv;
}

// ---------------- fused pairwise distance + top-9 smallest
// 256 threads, 64 n-rows per block; thread = 2 rows x 8 m-cols.
// Branchless register-resident sorted top-9 (static indexing only).
__device__ __forceinline__ void ins9(float v, int m, float tv[KK], int ti[KK])
{
    bool c[KK];
    #pragma unroll
    for (int k = 0; k < KK; k++) c[k] = v < tv[k];
    tv[8] = c[8] ? (c[7] ? tv[7] : v) : tv[8];
    ti[8] = c[8] ? (c[7] ? ti[7] : m) : ti[8];
    #pragma unroll
    for (int k = 7; k >= 1; k--) {
        tv[k] = c[k - 1] ? tv[k - 1] : (c[k] ? v : tv[k]);
        ti[k] = c[k - 1] ? ti[k - 1] : (c[k] ? m : ti[k]);
    }
    tv[0] = c[0] ? v : tv[0];
    ti[0] = c[0] ? m : ti[0];
}

__global__ __launch_bounds__(256, 3) void dist_topk_kernel(
    const float* __restrict__ xn, const float* __restrict__ sq,
    const float* __restrict__ rp, int* __restrict__ oidx)
{
    __shared__ float smem_all[CC * 64 * 2];   // 48 KB
    float* Xn_s = smem_all;            // [c][64 n-rows]
    float* sh2  = smem_all + CC * 64;  // [c][64 m]; reused for merge

    int b = blockIdx.y;
    int n0 = blockIdx.x * 64;
    int tid = threadIdx.x;
    int g   = tid >> 3;          // 0..31 row group
    int mc4 = (tid & 7) * 4;     // 0..28 col group (two float4 halves)
    int r0 = g * 2, r1 = r0 + 1;

    const float* xb = xn + (size_t)b * CC * NN;
    for (int t = tid; t < CC * 16; t += 256) {
        int c = t >> 4, q = (t & 15) * 4;
        *(float4*)&Xn_s[c * 64 + q] = *(const float4*)&xb[(size_t)c * NN + n0 + q];
    }
    __syncthreads();

    float2 sqn2 = *(const float2*)&sq[b * NN + n0 + r0];
    float sqn0 = sqn2.x, sqn1 = sqn2.y;

    float tv0[KK], tv1[KK]; int ti0[KK], ti1[KK];
    #pragma unroll
    for (int k = 0; k < KK; k++) { tv0[k] = 1e30f; tv1[k] = 1e30f; ti0[k] = 0; ti1[k] = 0; }

    for (int m0 = 0; m0 < NN; m0 += 64) {
        __syncthreads();
        for (int t = tid; t < CC * 16; t += 256) {
            int c = t >> 4, q = (t & 15) * 4;
            *(float4*)&sh2[c * 64 + q] = *(const float4*)&xb[(size_t)c * NN + m0 + q];
        }
        __syncthreads();
        ull acc0[4], acc1[4];
        #pragma unroll
        for (int j = 0; j < 4; j++) { acc0[j] = 0ull; acc1[j] = 0ull; }
        #pragma unroll 8
        for (int c = 0; c < CC; c++) {
            float2 a = *(const float2*)&Xn_s[c * 64 + r0];              // broadcast
            ulonglong2 blp = *(const ulonglong2*)&sh2[c * 64 + mc4];    // free pairs
            ulonglong2 brp = *(const ulonglong2*)&sh2[c * 64 + 32 + mc4];
            ull bp[4] = {blp.x, blp.y, brp.x, brp.y};
            ull a0 = pack2(a.x, a.x), a1 = pack2(a.y, a.y);
            #pragma unroll
            for (int j = 0; j < 4; j++) {
                ffma2(acc0[j], a0, bp[j]);
                ffma2(acc1[j], a1, bp[j]);
            }
        }
        // epilogue: dist + branchless topk insert (16B-aligned vector loads)
        const float* sqm = sq + b * NN + m0;
        float4 sqL = *(const float4*)&sqm[mc4];
        float4 sqR = *(const float4*)&sqm[32 + mc4];
        float sv[8] = {sqL.x, sqL.y, sqL.z, sqL.w, sqR.x, sqR.y, sqR.z, sqR.w};
        const float* rpr0 = rp + (size_t)(n0 + r0) * NN + m0;
        const float* rpr1 = rp + (size_t)(n0 + r1) * NN + m0;
        float4 rp0L = *(const float4*)&rpr0[mc4];
        float4 rp0R = *(const float4*)&rpr0[32 + mc4];
        float4 rp1L = *(const float4*)&rpr1[mc4];
        float4 rp1R = *(const float4*)&rpr1[32 + mc4];
        float r0v[8] = {rp0L.x, rp0L.y, rp0L.z, rp0L.w, rp0R.x, rp0R.y, rp0R.z, rp0R.w};
        float r1v[8] = {rp1L.x, rp1L.y, rp1L.z, rp1L.w, rp1R.x, rp1R.y, rp1R.z, rp1R.w};
        float2 p00 = unpack2(acc0[0]), p01 = unpack2(acc0[1]);
        float2 p02 = unpack2(acc0[2]), p03 = unpack2(acc0[3]);
        float2 p10 = unpack2(acc1[0]), p11 = unpack2(acc1[1]);
        float2 p12 = unpack2(acc1[2]), p13 = unpack2(acc1[3]);
        float dot0[8] = {p00.x, p00.y, p01.x, p01.y, p02.x, p02.y, p03.x, p03.y};
        float dot1[8] = {p10.x, p10.y, p11.x, p11.y, p12.x, p12.y, p13.x, p13.y};
        #pragma unroll
        for (int j = 0; j < 8; j++) {
            int m = m0 + (j < 4 ? mc4 + j : 32 + mc4 + (j - 4));
            float d0 = fmaf(-2.f, dot0[j], sqn0 + sv[j] + r0v[j]);
            float d1 = fmaf(-2.f, dot1[j], sqn1 + sv[j] + r1v[j]);
            ins9(d0, m, tv0, ti0);
            ins9(d1, m, tv1, ti1);
        }
    }

    // ---------- merge: 8 sorted partial lists per row, single pass ----------
    __syncthreads();
    float* cv = smem_all;                        // [64][8][9] values (4608 f)
    int*   ci = (int*)(smem_all + 64 * 8 * KK);  // [64][8][9] indices
    int cg = tid & 7;
    #pragma unroll
    for (int k = 0; k < KK; k++) {
        cv[(r0 * 8 + cg) * KK + k] = tv0[k]; ci[(r0 * 8 + cg) * KK + k] = ti0[k];
        cv[(r1 * 8 + cg) * KK + k] = tv1[k]; ci[(r1 * 8 + cg) * KK + k] = ti1[k];
    }
    __syncthreads();
    if (tid < 64) {
        float* rv = cv + tid * 8 * KK;
        int*   ri = ci + tid * 8 * KK;
        int* op = oidx + ((size_t)b * NN + n0 + tid) * KK;
        for (int k = 0; k < KK; k++) {
            float best = 2e30f; int bi = 0, bt = 0;
            for (int t = 0; t < 8 * KK; t++) {
                float v = rv[t];
                if (v < best) { best = v; bi = ri[t]; bt = t; }
            }
            rv[bt] = 3e30f;   // consume
            op[k] = bi;
        }
    }
}

// ---------------- gather neighbors, max(x_j - x_i), write channel-interleaved (B,2C,N)
__global__ __launch_bounds__(256) void aggregate_kernel(
    const float* __restrict__ xf, const int* __restrict__ idx, float* __restrict__ y)
{
    int bc = blockIdx.x;            // b*CC + c
    __shared__ float row[NN];
    const float* p = xf + (size_t)bc * NN;
    for (int i = threadIdx.x; i < NN; i += 256) row[i] = p[i];
    __syncthreads();
    int b = bc / CC, c = bc - b * CC;
    const int* ip = idx + (size_t)b * NN * KK;
    float* y0 = y + ((size_t)b * C2 + 2 * c) * NN;
    float* y1 = y0 + NN;
    for (int n = threadIdx.x; n < NN; n += 256) {
        float xi = row[n];
        float mx = -3e38f;
        #pragma unroll
        for (int k = 0; k < KK; k++) {
            int j = ip[n * KK + k];
            mx = fmaxf(mx, row[j] - xi);
        }
        y0[n] = xi;
        y1[n] = mx;
    }
}

// ---------------- host orchestration ----------------
static void run_conv(const float* X, const float* W, const float* bias,
                     float* out, int Cout, int Cin)
{
    dim3 g(NN / 64, (Cout + 63) / 64, BB);
    gemm_bias_kernel<<<g, 128>>>(X, W, bias, out, Cout, Cin);
}
static void run_inorm(const float* in, float* out, const float* res, int Crows, int act)
{
    inorm_kernel<<<BB * Crows, 256>>>(in, out, res, act);
}

extern "C" void kernel_launch(void* const* d_in, const int* in_sizes, int n_in,
                              void* d_out, int out_size)
{
    (void)in_sizes; (void)n_in; (void)out_size;
    const float* x  = (const float*)d_in[0];
    const float* rp = (const float*)d_in[1];
    const float* P[20];
    for (int i = 0; i < 20; i++) P[i] = (const float*)d_in[2 + i];

    float *act, *t1, *xf, *xnp, *sqp, *big; int* idxp;
    cudaGetSymbolAddress((void**)&act,  g_act);
    cudaGetSymbolAddress((void**)&t1,   g_t1);
    cudaGetSymbolAddress((void**)&xf,   g_xf);
    cudaGetSymbolAddress((void**)&xnp,  g_xn);
    cudaGetSymbolAddress((void**)&sqp,  g_sq);
    cudaGetSymbolAddress((void**)&idxp, g_idx);
    cudaGetSymbolAddress((void**)&big,  g_big);
    float* y2 = big;                          // (B,2C,N)
    float* t3 = big + (size_t)BB * C2 * NN;   // (B,2C,N)
    float* out = (float*)d_out;

    auto grapher = [&](const float* inx,
                       const float* w1, const float* b1,
                       const float* mw, const float* mb,
                       const float* w2, const float* b2, float* outp) {
        run_conv(inx, w1, b1, t1, CC, CC);
        run_inorm(t1, xf, nullptr, CC, 0);                          // xf
        l2norm_kernel<<<(BB * NN + 255) / 256, 256>>>(xf, xnp, sqp);
        dim3 dg(NN / 64, BB);
        dist_topk_kernel<<<dg, 256>>>(xnp, sqp, rp, idxp);
        aggregate_kernel<<<BB * CC, 256>>>(xf, idxp, y2);           // (B,2C,N)
        run_conv(y2, mw, mb, t3, C2, C2);
        run_inorm(t3, t3, nullptr, C2, 1);                          // gelu, in-place
        run_conv(t3, w2, b2, t1, CC, C2);
        run_inorm(t1, outp, inx, CC, 0);                            // + shortcut
    };
    auto ffn = [&](float* a, const float* w1, const float* b1,
                   const float* w2, const float* b2) {
        run_conv(a, w1, b1, big, C4, CC);
        run_inorm(big, big, nullptr, C4, 1);                        // gelu, in-place
        run_conv(big, w2, b2, t1, CC, C4);
        run_inorm(t1, a, a, CC, 0);                                 // + shortcut
    };

    grapher(x, P[0], P[1], P[2], P[3], P[4], P[5], act);
    ffn(act, P[12], P[13], P[14], P[15]);
    run_inorm(act, act, nullptr, CC, 2);                            // relu(inorm)
    grapher(act, P[6], P[7], P[8], P[9], P[10], P[11], act);
    ffn(act, P[16], P[17], P[18], P[19]);
    run_inorm(act, out, x, CC, 0);                                  // x + inorm(y)
}